// round 14
// baseline (speedup 1.0000x reference)
#include <cuda_runtime.h>

// ---------------- problem constants ----------------
#define NHEADS 4
#define KDIM   16
#define RESV   40
#define DIMC   256
#define HDC    64
#define DV     64
#define NPIX   1600
#define BATCH  16
#define EPSBN  1e-5f
#define SCALEF 0.25f

typedef unsigned long long ull;

// ---------------- scratch ----------------
__device__ float g_xi [BATCH*HDC*NPIX];
__device__ float g_q  [BATCH*KDIM*NPIX];
__device__ float g_k  [BATCH*KDIM*NPIX];
__device__ float g_vt [BATCH*NPIX*DV];      // [b][p][d]
__device__ float g_cat[BATCH*DIMC*NPIX];

// ---------------- f32x2 helpers ----------------
__device__ __forceinline__ ull f2pack(float x, float y){
    ull r; asm("mov.b64 %0, {%1, %2};" : "=l"(r) : "f"(x), "f"(y)); return r;
}
__device__ __forceinline__ float2 f2unpack(ull u){
    float2 r; asm("mov.b64 {%0, %1}, %2;" : "=f"(r.x), "=f"(r.y) : "l"(u)); return r;
}
__device__ __forceinline__ ull ffma2(ull a, ull b, ull c){
    ull r; asm("fma.rn.f32x2 %0, %1, %2, %3;" : "=l"(r) : "l"(a), "l"(b), "l"(c)); return r;
}
__device__ __forceinline__ ull fmul2(ull a, ull b){
    ull r; asm("mul.rn.f32x2 %0, %1, %2;" : "=l"(r) : "l"(a), "l"(b)); return r;
}

// ---------------- cp.async helpers ----------------
__device__ __forceinline__ void cp16(void* dst, const void* src){
    unsigned s = (unsigned)__cvta_generic_to_shared(dst);
    asm volatile("cp.async.cg.shared.global [%0], [%1], 16;" :: "r"(s), "l"(src));
}
#define CP_COMMIT() asm volatile("cp.async.commit_group;" ::: "memory")
#define CP_WAIT0()  asm volatile("cp.async.wait_group 0;"  ::: "memory")

// ================= 1) depthwise 5x5 conv + BN (+ cascade add) ================
__global__ __launch_bounds__(256) void dwconv_kernel(
    const float* __restrict__ x,
    const float* __restrict__ dw_w,
    const float* __restrict__ dw_g, const float* __restrict__ dw_b,
    const float* __restrict__ dw_m, const float* __restrict__ dw_v,
    int head)
{
    __shared__ float tile[44*44];
    __shared__ float wsh[25];

    const int tid = threadIdx.x;
    const int c   = blockIdx.x & 63;
    const int b   = blockIdx.x >> 6;
    const int ci  = head*HDC + c;

    const float* xs = x + ((size_t)b*DIMC + ci) * NPIX;
    const float s   = dw_g[ci] * rsqrtf(dw_v[ci] + EPSBN);
    const float bias = dw_b[ci] - dw_m[ci]*s;

    for (int t = tid; t < 44*44; t += 256) tile[t] = 0.f;
    if (tid < 25) wsh[tid] = dw_w[(size_t)ci*25 + tid] * s;
    __syncthreads();
    for (int t = tid; t < NPIX; t += 256){
        int h = t / 40, w = t - h*40;
        tile[(h+2)*44 + (w+2)] = xs[t];
    }
    __syncthreads();

    const float* prev = g_cat + ((size_t)b*DIMC + (head-1)*DV + c)*NPIX;
    float* xo = g_xi + ((size_t)b*HDC + c)*NPIX;

    for (int g = tid; g < 400; g += 256){
        int h  = g / 10;
        int w4 = (g - h*10) * 4;
        float o0 = bias, o1 = bias, o2 = bias, o3 = bias;
        #pragma unroll
        for (int ky = 0; ky < 5; ky++){
            const float* rp = &tile[(h+ky)*44 + w4];
            float4 A = *(const float4*)rp;
            float4 B = *(const float4*)(rp + 4);
            float a0=A.x,a1=A.y,a2=A.z,a3=A.w,a4=B.x,a5=B.y,a6=B.z,a7=B.w;
            float w0=wsh[ky*5+0], w1=wsh[ky*5+1], w2=wsh[ky*5+2],
                  w3=wsh[ky*5+3], w4v=wsh[ky*5+4];
            o0 = fmaf(a0,w0, fmaf(a1,w1, fmaf(a2,w2, fmaf(a3,w3, fmaf(a4,w4v, o0)))));
            o1 = fmaf(a1,w0, fmaf(a2,w1, fmaf(a3,w2, fmaf(a4,w3, fmaf(a5,w4v, o1)))));
            o2 = fmaf(a2,w0, fmaf(a3,w1, fmaf(a4,w2, fmaf(a5,w3, fmaf(a6,w4v, o2)))));
            o3 = fmaf(a3,w0, fmaf(a4,w1, fmaf(a5,w2, fmaf(a6,w3, fmaf(a7,w4v, o3)))));
        }
        int p = h*40 + w4;
        if (head > 0){
            float4 pv = *(const float4*)&prev[p];
            o0 += pv.x; o1 += pv.y; o2 += pv.z; o3 += pv.w;
        }
        float4 r; r.x=o0; r.y=o1; r.z=o2; r.w=o3;
        *(float4*)&xo[p] = r;
    }
}

// ================= 2) QKV projections + BN (f32x2) ===========================
#define QKV_T 320
#define QKV_SMEM (64*320*4 + 48*64*8)

__global__ __launch_bounds__(QKV_T) void qkv_kernel(
    const float* __restrict__ q_w, const float* __restrict__ q_g,
    const float* __restrict__ q_b, const float* __restrict__ q_m,
    const float* __restrict__ q_v,
    const float* __restrict__ k_w, const float* __restrict__ k_g,
    const float* __restrict__ k_b, const float* __restrict__ k_m,
    const float* __restrict__ k_v,
    const float* __restrict__ v_w, const float* __restrict__ v_g,
    const float* __restrict__ v_b, const float* __restrict__ v_m,
    const float* __restrict__ v_v,
    int head)
{
    extern __shared__ float sm[];
    float* xt  = sm;                       // [64][320]
    ull*   wsm = (ull*)(sm + 64*320);      // [48][64] packed {w,w}

    const int tid = threadIdx.x;
    const int b   = blockIdx.y;
    const int z   = blockIdx.z;
    const int p0  = blockIdx.x * 320;

    const float* xb = g_xi + (size_t)b*HDC*NPIX + p0;
    for (int t = tid; t < 64*320; t += QKV_T){
        int c = t / 320, pp2 = t % 320;
        xt[t] = xb[(size_t)c*NPIX + pp2];
    }
    for (int t = tid; t < 48*64; t += QKV_T){
        int jl = t / 64, cc = t % 64;
        int jr = z*48 + jl;
        float wv;
        if (jr < 16)      wv = q_w[(size_t)(head*16 + jr)      *64 + cc];
        else if (jr < 32) wv = k_w[(size_t)(head*16 + jr - 16) *64 + cc];
        else              wv = v_w[(size_t)(head*64 + jr - 32) *64 + cc];
        wsm[t] = f2pack(wv, wv);
    }
    __syncthreads();

    const int pp   = tid % 160;
    const int jsub = tid / 160;
    const int px   = p0 + 2*pp;

    for (int jg = 0; jg < 3; jg++){
        const int jl = jsub*24 + jg*8;
        ull acc2[8];
        #pragma unroll
        for (int k = 0; k < 8; k++) acc2[k] = 0ull;

        for (int c = 0; c < 64; c++){
            ull xv2 = *(const ull*)&xt[c*320 + 2*pp];
            const ull* wr = &wsm[jl*64 + c];
            #pragma unroll
            for (int k = 0; k < 8; k++)
                acc2[k] = ffma2(wr[k*64], xv2, acc2[k]);
        }
        #pragma unroll
        for (int k = 0; k < 8; k++){
            float2 a = f2unpack(acc2[k]);
            int jr = z*48 + jl + k;
            if (jr < 16){
                int q = head*16 + jr;
                float sc = q_g[q]*rsqrtf(q_v[q]+EPSBN);
                float mu = q_m[q], be = q_b[q];
                g_q[((size_t)b*16 + jr)*NPIX + px]     = (a.x-mu)*sc + be;
                g_q[((size_t)b*16 + jr)*NPIX + px + 1] = (a.y-mu)*sc + be;
            } else if (jr < 32){
                int q = head*16 + jr - 16;
                float sc = k_g[q]*rsqrtf(k_v[q]+EPSBN);
                float mu = k_m[q], be = k_b[q];
                g_k[((size_t)b*16 + (jr-16))*NPIX + px]     = (a.x-mu)*sc + be;
                g_k[((size_t)b*16 + (jr-16))*NPIX + px + 1] = (a.y-mu)*sc + be;
            } else {
                int d = jr - 32;
                int q = head*64 + d;
                float sc = v_g[q]*rsqrtf(v_v[q]+EPSBN);
                float mu = v_m[q], be = v_b[q];
                g_vt[((size_t)b*NPIX + px)    *64 + d] = (a.x-mu)*sc + be;
                g_vt[((size_t)b*NPIX + px + 1)*64 + d] = (a.y-mu)*sc + be;
            }
        }
    }
}

// ================= 3) fused flash attention (dim-split AV, 32-row blocks) ====
// 32 query rows / block (lane = row), chunk = 80 keys, 20 chunks, 8 warps.
// QK: warp w computes keys [w*10, w*10+10); probs stored PRE-PACKED {p,p}
//     into ps2[80][32] (STS.64, conflict-free). Bias via warp-uniform LDG.
// AV: warp w owns dims [w*8, w*8+8) for ALL rows; V loads warp-uniform.
// 800 blocks at occ=2 -> 90% wave utilization (vs 68% at 400 blocks).
// smem floats: ks 2x[16][80]=2560 | vs 2x[80][64]=10240 |
//   qs2 ull[16][32] @12800 (1024f) | ps2 ull[80][32] @13824 (5120f) |
//   rr [8][32] @18944  -> 19200 floats = 76.8 KB
#define ATTN_SMEM (19200*4)

__global__ __launch_bounds__(256, 2) void attn_kernel(
    const float* __restrict__ attn_bias, int head)
{
    extern __shared__ float sm[];
    float* ks  = sm;
    float* vs  = sm + 2560;
    ull*   qs2 = (ull*)(sm + 12800);
    ull*   ps2 = (ull*)(sm + 13824);
    float* rr  = sm + 18944;

    const int tid   = threadIdx.x;
    const int lane  = tid & 31;
    const int w     = tid >> 5;
    const int b     = blockIdx.y;
    const int n0    = blockIdx.x * 32;
    const int k0    = w * 10;
    const int dbase = w * 8;

    const float* kb  = g_k  + (size_t)b*16*NPIX;
    const float* vb  = g_vt + (size_t)b*NPIX*64;
    const float* bib = attn_bias + (size_t)head*NPIX;

    // q tile packed {q,q}, scale folded
    for (int t = tid; t < 512; t += 256){
        int kd = t >> 5, r = t & 31;
        float qv = g_q[((size_t)b*16 + kd)*NPIX + n0 + r] * SCALEF;
        qs2[t] = f2pack(qv, qv);
    }

    // prologue: prefetch chunk 0 into buffer 0
    for (int t = tid; t < 320; t += 256){
        int kd = t / 20, mm = (t % 20) * 4;
        cp16(&ks[kd*80 + mm], &kb[(size_t)kd*NPIX + mm]);
    }
    for (int t = tid; t < 1280; t += 256){
        int m = t >> 4, d = (t & 15) * 4;
        cp16(&vs[m*64 + d], &vb[(size_t)m*64 + d]);
    }
    CP_COMMIT();

    ull out2[4] = {0ull, 0ull, 0ull, 0ull};
    float rm = -1e30f, rs = 0.f;

    for (int ch = 0; ch < 20; ch++){
        const int cur = ch & 1;
        const int m0  = ch * 80;
        const float* ksb = ks + cur*1280;
        const float* vsb = vs + cur*5120;

        CP_WAIT0();
        __syncthreads();                       // A: buffers[cur] ready+visible

        // ---- QK: 10 keys x 1 row; bias (warp-uniform LDG) folded in ----
        ull a[5];
        #pragma unroll
        for (int t = 0; t < 5; t++)
            a[t] = *(const ull*)&bib[m0 + k0 + 2*t];
        #pragma unroll
        for (int kd = 0; kd < 16; kd++){
            ull q2 = qs2[kd*32 + lane];
            const ull* kk = (const ull*)&ksb[kd*80 + k0];   // warp-uniform
            #pragma unroll
            for (int t = 0; t < 5; t++)
                a[t] = ffma2(q2, kk[t], a[t]);
        }
        float lmax = -1e30f;
        #pragma unroll
        for (int t = 0; t < 5; t++){
            float2 x = f2unpack(a[t]);
            lmax = fmaxf(lmax, fmaxf(x.x, x.y));
        }
        rr[w*32 + lane] = lmax;
        __syncthreads();                       // B: rr visible

        float nm = rm;
        #pragma unroll
        for (int j = 0; j < 8; j++) nm = fmaxf(nm, rr[j*32 + lane]);
        float corr = __expf(rm - nm);
        rm = nm;
        rs *= corr;
        {
            ull c2 = f2pack(corr, corr);
            #pragma unroll
            for (int i = 0; i < 4; i++) out2[i] = fmul2(out2[i], c2);
        }
        // exp + store pre-packed probs
        #pragma unroll
        for (int t = 0; t < 5; t++){
            float2 x = f2unpack(a[t]);
            float p0 = __expf(x.x - nm), p1 = __expf(x.y - nm);
            rs += p0 + p1;
            ps2[(k0 + 2*t)    *32 + lane] = f2pack(p0, p0);
            ps2[(k0 + 2*t + 1)*32 + lane] = f2pack(p1, p1);
        }

        // ---- prefetch next chunk (overlaps AV below) ----
        if (ch < 19){
            const int m1 = m0 + 80;
            float* ksn = ks + (1-cur)*1280;
            float* vsn = vs + (1-cur)*5120;
            for (int t = tid; t < 320; t += 256){
                int kd = t / 20, mm = (t % 20) * 4;
                cp16(&ksn[kd*80 + mm], &kb[(size_t)kd*NPIX + m1 + mm]);
            }
            for (int t = tid; t < 1280; t += 256){
                int m = t >> 4, d = (t & 15) * 4;
                cp16(&vsn[m*64 + d], &vb[(size_t)(m1 + m)*64 + d]);
            }
            CP_COMMIT();
        }
        __syncthreads();                       // C: ps2 visible to all warps

        // ---- AV: warp w accumulates dims [dbase, dbase+8) ----
        #pragma unroll 4
        for (int m = 0; m < 80; m++){
            ull p2 = ps2[m*32 + lane];
            const float* vrow = &vsb[m*64 + dbase];       // warp-uniform
            ulonglong2 va  = *(const ulonglong2*)vrow;
            ulonglong2 vb2 = *(const ulonglong2*)(vrow + 4);
            out2[0] = ffma2(va.x,  p2, out2[0]);
            out2[1] = ffma2(va.y,  p2, out2[1]);
            out2[2] = ffma2(vb2.x, p2, out2[2]);
            out2[3] = ffma2(vb2.y, p2, out2[3]);
        }
    }

    // ---- row-sum across warps ----
    rr[w*32 + lane] = rs;
    __syncthreads();
    float tot = 0.f;
    #pragma unroll
    for (int j = 0; j < 8; j++) tot += rr[j*32 + lane];
    ull i2 = f2pack(1.0f/tot, 1.0f/tot);

    // ---- direct output write: warp owns its dims exclusively ----
    float* ob = g_cat + ((size_t)b*DIMC + head*64 + dbase)*NPIX + n0;
    #pragma unroll
    for (int jj = 0; jj < 4; jj++){
        float2 f = f2unpack(fmul2(out2[jj], i2));
        ob[(size_t)(2*jj)    *NPIX + lane] = f.x;
        ob[(size_t)(2*jj + 1)*NPIX + lane] = f.y;
    }
}

// ================= 4) final 256x256 projection + BN + ReLU (f32x2) ==========
#define PROJ_SMEM (64*65*8 + 64*64*4)

__global__ __launch_bounds__(256) void proj_kernel(
    const float* __restrict__ W,
    const float* __restrict__ pg, const float* __restrict__ pb,
    const float* __restrict__ pm, const float* __restrict__ pvv,
    float* __restrict__ out)
{
    extern __shared__ float smp[];
    ull*   Wt2 = (ull*)smp;                // [64][65] packed {w,w}
    float* Xt  = smp + 64*65*2;            // [64][64]

    const int tid = threadIdx.x;
    const int n0 = blockIdx.x * 64;
    const int o0 = blockIdx.y * 64;
    const int b  = blockIdx.z;
    const int tn = tid % 16, to = tid / 16;

    ull acc2[4][2];
    #pragma unroll
    for (int i = 0; i < 4; i++){ acc2[i][0] = 0ull; acc2[i][1] = 0ull; }

    for (int c0 = 0; c0 < 256; c0 += 64){
        __syncthreads();
        for (int t = tid; t < 4096; t += 256){
            int i = t / 64, j = t % 64;
            float wv = W[(size_t)(o0 + i)*256 + c0 + j];
            Wt2[i*65 + j] = f2pack(wv, wv);
            Xt[i*64 + j]  = g_cat[((size_t)b*DIMC + c0 + i)*NPIX + n0 + j];
        }
        __syncthreads();
        for (int c = 0; c < 64; c++){
            ull bx01 = *(const ull*)&Xt[c*64 + tn*4];
            ull bx23 = *(const ull*)&Xt[c*64 + tn*4 + 2];
            #pragma unroll
            for (int i = 0; i < 4; i++){
                ull a2 = Wt2[(to*4 + i)*65 + c];
                acc2[i][0] = ffma2(a2, bx01, acc2[i][0]);
                acc2[i][1] = ffma2(a2, bx23, acc2[i][1]);
            }
        }
    }
    #pragma unroll
    for (int i = 0; i < 4; i++){
        int o = o0 + to*4 + i;
        float s  = pg[o] * rsqrtf(pvv[o] + EPSBN);
        float mu = pm[o], be = pb[o];
        float2 a = f2unpack(acc2[i][0]);
        float2 c = f2unpack(acc2[i][1]);
        float4 v4;
        v4.x = fmaxf((a.x-mu)*s + be, 0.f);
        v4.y = fmaxf((a.y-mu)*s + be, 0.f);
        v4.z = fmaxf((c.x-mu)*s + be, 0.f);
        v4.w = fmaxf((c.y-mu)*s + be, 0.f);
        *(float4*)&out[((size_t)b*DIMC + o)*NPIX + n0 + tn*4] = v4;
    }
}

// ================= launch ====================================================
extern "C" void kernel_launch(void* const* d_in, const int* in_sizes, int n_in,
                              void* d_out, int out_size)
{
    const float* x      = (const float*)d_in[0];
    const float* dw_w   = (const float*)d_in[1];
    const float* dw_g   = (const float*)d_in[2];
    const float* dw_b   = (const float*)d_in[3];
    const float* dw_m   = (const float*)d_in[4];
    const float* dw_v   = (const float*)d_in[5];
    const float* q_w    = (const float*)d_in[6];
    const float* q_g    = (const float*)d_in[7];
    const float* q_b    = (const float*)d_in[8];
    const float* q_m    = (const float*)d_in[9];
    const float* q_v    = (const float*)d_in[10];
    const float* k_w    = (const float*)d_in[11];
    const float* k_g    = (const float*)d_in[12];
    const float* k_b    = (const float*)d_in[13];
    const float* k_m    = (const float*)d_in[14];
    const float* k_v    = (const float*)d_in[15];
    const float* v_w    = (const float*)d_in[16];
    const float* v_g    = (const float*)d_in[17];
    const float* v_b    = (const float*)d_in[18];
    const float* v_m    = (const float*)d_in[19];
    const float* v_v    = (const float*)d_in[20];
    const float* proj_w = (const float*)d_in[21];
    const float* proj_g = (const float*)d_in[22];
    const float* proj_b = (const float*)d_in[23];
    const float* proj_m = (const float*)d_in[24];
    const float* proj_v = (const float*)d_in[25];
    const float* attn_b = (const float*)d_in[26];

    cudaFuncSetAttribute(qkv_kernel,
        cudaFuncAttributeMaxDynamicSharedMemorySize, QKV_SMEM);
    cudaFuncSetAttribute(attn_kernel,
        cudaFuncAttributeMaxDynamicSharedMemorySize, ATTN_SMEM);
    cudaFuncSetAttribute(proj_kernel,
        cudaFuncAttributeMaxDynamicSharedMemorySize, PROJ_SMEM);

    for (int head = 0; head < NHEADS; head++){
        dwconv_kernel<<<BATCH*HDC, 256>>>(
            x, dw_w, dw_g, dw_b, dw_m, dw_v, head);
        qkv_kernel<<<dim3(5, BATCH, 2), QKV_T, QKV_SMEM>>>(
            q_w, q_g, q_b, q_m, q_v,
            k_w, k_g, k_b, k_m, k_v,
            v_w, v_g, v_b, v_m, v_v, head);
        attn_kernel<<<dim3(50, BATCH), 256, ATTN_SMEM>>>(attn_b, head);
    }
    proj_kernel<<<dim3(25, 4, BATCH), 256, PROJ_SMEM>>>(
        proj_w, proj_g, proj_b, proj_m, proj_v, (float*)d_out);
}

// round 16
// speedup vs baseline: 1.3075x; 1.3075x over previous
#include <cuda_runtime.h>

// ---------------- problem constants ----------------
#define NHEADS 4
#define KDIM   16
#define RESV   40
#define DIMC   256
#define HDC    64
#define DV     64
#define NPIX   1600
#define BATCH  16
#define EPSBN  1e-5f
#define SCALEF 0.25f

typedef unsigned long long ull;

// ---------------- scratch (16B-aligned for bulk-copy sources) ----------------
__device__ __align__(16) float g_xi [BATCH*HDC*NPIX];
__device__ __align__(16) float g_q  [BATCH*KDIM*NPIX];
__device__ __align__(16) float g_k  [BATCH*KDIM*NPIX];
__device__ __align__(16) float g_vt [BATCH*NPIX*DV];      // [b][p][d]
__device__ __align__(16) float g_cat[BATCH*DIMC*NPIX];

// ---------------- f32x2 helpers ----------------
__device__ __forceinline__ ull f2pack(float x, float y){
    ull r; asm("mov.b64 %0, {%1, %2};" : "=l"(r) : "f"(x), "f"(y)); return r;
}
__device__ __forceinline__ float2 f2unpack(ull u){
    float2 r; asm("mov.b64 {%0, %1}, %2;" : "=f"(r.x), "=f"(r.y) : "l"(u)); return r;
}
__device__ __forceinline__ ull ffma2(ull a, ull b, ull c){
    ull r; asm("fma.rn.f32x2 %0, %1, %2, %3;" : "=l"(r) : "l"(a), "l"(b), "l"(c)); return r;
}
__device__ __forceinline__ ull fmul2(ull a, ull b){
    ull r; asm("mul.rn.f32x2 %0, %1, %2;" : "=l"(r) : "l"(a), "l"(b)); return r;
}

// ---------------- bulk-async + mbarrier helpers ----------------
__device__ __forceinline__ unsigned smem_u32(const void* p){
    return (unsigned)__cvta_generic_to_shared(p);
}
__device__ __forceinline__ void mbar_init(unsigned mbar, unsigned cnt){
    asm volatile("mbarrier.init.shared.b64 [%0], %1;" :: "r"(mbar), "r"(cnt) : "memory");
}
__device__ __forceinline__ void mbar_expect_tx(unsigned mbar, unsigned bytes){
    asm volatile("mbarrier.arrive.expect_tx.shared.b64 _, [%0], %1;"
                 :: "r"(mbar), "r"(bytes) : "memory");
}
__device__ __forceinline__ void mbar_wait(unsigned mbar, unsigned parity){
    asm volatile(
        "{\n\t.reg .pred P;\n\t"
        "W_%=:\n\t"
        "mbarrier.try_wait.parity.acquire.cta.shared::cta.b64 P, [%0], %1, 0x989680;\n\t"
        "@!P bra W_%=;\n\t"
        "}" :: "r"(mbar), "r"(parity) : "memory");
}
__device__ __forceinline__ void cpbulk(unsigned dst, const void* src,
                                       unsigned bytes, unsigned mbar){
    asm volatile(
        "cp.async.bulk.shared::cta.global.mbarrier::complete_tx::bytes [%0], [%1], %2, [%3];"
        :: "r"(dst), "l"(src), "r"(bytes), "r"(mbar) : "memory");
}
__device__ __forceinline__ void fence_async(){
    asm volatile("fence.proxy.async.shared::cta;" ::: "memory");
}

// ================= 1) depthwise 5x5 conv + BN (+ cascade add) ================
__global__ __launch_bounds__(256) void dwconv_kernel(
    const float* __restrict__ x,
    const float* __restrict__ dw_w,
    const float* __restrict__ dw_g, const float* __restrict__ dw_b,
    const float* __restrict__ dw_m, const float* __restrict__ dw_v,
    int head)
{
    __shared__ float tile[44*44];
    __shared__ float wsh[25];

    const int tid = threadIdx.x;
    const int c   = blockIdx.x & 63;
    const int b   = blockIdx.x >> 6;
    const int ci  = head*HDC + c;

    const float* xs = x + ((size_t)b*DIMC + ci) * NPIX;
    const float s   = dw_g[ci] * rsqrtf(dw_v[ci] + EPSBN);
    const float bias = dw_b[ci] - dw_m[ci]*s;

    for (int t = tid; t < 44*44; t += 256) tile[t] = 0.f;
    if (tid < 25) wsh[tid] = dw_w[(size_t)ci*25 + tid] * s;
    __syncthreads();
    for (int t = tid; t < NPIX; t += 256){
        int h = t / 40, w = t - h*40;
        tile[(h+2)*44 + (w+2)] = xs[t];
    }
    __syncthreads();

    const float* prev = g_cat + ((size_t)b*DIMC + (head-1)*DV + c)*NPIX;
    float* xo = g_xi + ((size_t)b*HDC + c)*NPIX;

    for (int g = tid; g < 400; g += 256){
        int h  = g / 10;
        int w4 = (g - h*10) * 4;
        float o0 = bias, o1 = bias, o2 = bias, o3 = bias;
        #pragma unroll
        for (int ky = 0; ky < 5; ky++){
            const float* rp = &tile[(h+ky)*44 + w4];
            float4 A = *(const float4*)rp;
            float4 B = *(const float4*)(rp + 4);
            float a0=A.x,a1=A.y,a2=A.z,a3=A.w,a4=B.x,a5=B.y,a6=B.z,a7=B.w;
            float w0=wsh[ky*5+0], w1=wsh[ky*5+1], w2=wsh[ky*5+2],
                  w3=wsh[ky*5+3], w4v=wsh[ky*5+4];
            o0 = fmaf(a0,w0, fmaf(a1,w1, fmaf(a2,w2, fmaf(a3,w3, fmaf(a4,w4v, o0)))));
            o1 = fmaf(a1,w0, fmaf(a2,w1, fmaf(a3,w2, fmaf(a4,w3, fmaf(a5,w4v, o1)))));
            o2 = fmaf(a2,w0, fmaf(a3,w1, fmaf(a4,w2, fmaf(a5,w3, fmaf(a6,w4v, o2)))));
            o3 = fmaf(a3,w0, fmaf(a4,w1, fmaf(a5,w2, fmaf(a6,w3, fmaf(a7,w4v, o3)))));
        }
        int p = h*40 + w4;
        if (head > 0){
            float4 pv = *(const float4*)&prev[p];
            o0 += pv.x; o1 += pv.y; o2 += pv.z; o3 += pv.w;
        }
        float4 r; r.x=o0; r.y=o1; r.z=o2; r.w=o3;
        *(float4*)&xo[p] = r;
    }
}

// ================= 2) QKV projections + BN (f32x2) ===========================
#define QKV_T 320
#define QKV_SMEM (64*320*4 + 48*64*8)

__global__ __launch_bounds__(QKV_T) void qkv_kernel(
    const float* __restrict__ q_w, const float* __restrict__ q_g,
    const float* __restrict__ q_b, const float* __restrict__ q_m,
    const float* __restrict__ q_v,
    const float* __restrict__ k_w, const float* __restrict__ k_g,
    const float* __restrict__ k_b, const float* __restrict__ k_m,
    const float* __restrict__ k_v,
    const float* __restrict__ v_w, const float* __restrict__ v_g,
    const float* __restrict__ v_b, const float* __restrict__ v_m,
    const float* __restrict__ v_v,
    int head)
{
    extern __shared__ float sm[];
    float* xt  = sm;                       // [64][320]
    ull*   wsm = (ull*)(sm + 64*320);      // [48][64] packed {w,w}

    const int tid = threadIdx.x;
    const int b   = blockIdx.y;
    const int z   = blockIdx.z;
    const int p0  = blockIdx.x * 320;

    const float* xb = g_xi + (size_t)b*HDC*NPIX + p0;
    for (int t = tid; t < 64*320; t += QKV_T){
        int c = t / 320, pp2 = t % 320;
        xt[t] = xb[(size_t)c*NPIX + pp2];
    }
    for (int t = tid; t < 48*64; t += QKV_T){
        int jl = t / 64, cc = t % 64;
        int jr = z*48 + jl;
        float wv;
        if (jr < 16)      wv = q_w[(size_t)(head*16 + jr)      *64 + cc];
        else if (jr < 32) wv = k_w[(size_t)(head*16 + jr - 16) *64 + cc];
        else              wv = v_w[(size_t)(head*64 + jr - 32) *64 + cc];
        wsm[t] = f2pack(wv, wv);
    }
    __syncthreads();

    const int pp   = tid % 160;
    const int jsub = tid / 160;
    const int px   = p0 + 2*pp;

    for (int jg = 0; jg < 3; jg++){
        const int jl = jsub*24 + jg*8;
        ull acc2[8];
        #pragma unroll
        for (int k = 0; k < 8; k++) acc2[k] = 0ull;

        for (int c = 0; c < 64; c++){
            ull xv2 = *(const ull*)&xt[c*320 + 2*pp];
            const ull* wr = &wsm[jl*64 + c];
            #pragma unroll
            for (int k = 0; k < 8; k++)
                acc2[k] = ffma2(wr[k*64], xv2, acc2[k]);
        }
        #pragma unroll
        for (int k = 0; k < 8; k++){
            float2 a = f2unpack(acc2[k]);
            int jr = z*48 + jl + k;
            if (jr < 16){
                int q = head*16 + jr;
                float sc = q_g[q]*rsqrtf(q_v[q]+EPSBN);
                float mu = q_m[q], be = q_b[q];
                g_q[((size_t)b*16 + jr)*NPIX + px]     = (a.x-mu)*sc + be;
                g_q[((size_t)b*16 + jr)*NPIX + px + 1] = (a.y-mu)*sc + be;
            } else if (jr < 32){
                int q = head*16 + jr - 16;
                float sc = k_g[q]*rsqrtf(k_v[q]+EPSBN);
                float mu = k_m[q], be = k_b[q];
                g_k[((size_t)b*16 + (jr-16))*NPIX + px]     = (a.x-mu)*sc + be;
                g_k[((size_t)b*16 + (jr-16))*NPIX + px + 1] = (a.y-mu)*sc + be;
            } else {
                int d = jr - 32;
                int q = head*64 + d;
                float sc = v_g[q]*rsqrtf(v_v[q]+EPSBN);
                float mu = v_m[q], be = v_b[q];
                g_vt[((size_t)b*NPIX + px)    *64 + d] = (a.x-mu)*sc + be;
                g_vt[((size_t)b*NPIX + px + 1)*64 + d] = (a.y-mu)*sc + be;
            }
        }
    }
}

// ================= 3) fused flash attention (dim-split AV + bulk async) ======
// 64 query rows / block, chunk = 80 keys, 20 chunks, 8 warps (R13 structure).
// K/V chunk fill via cp.async.bulk (17 descriptors, ONE issuing thread, one
// mbarrier expect_tx of 25600 B) instead of 1600 per-thread LDGSTS ops.
// FIX vs R15: __syncthreads() after the qs2 fill — the per-thread mbar_wait
// does NOT order other threads' generic smem stores (that ordering used to
// come from the removed barrier A).
// smem floats: ks 2x[16][80] @0 | vs 2x[80][64] @2560 | qs2 ull[16][64] @12800
//   | ps2 ull[80][66] @14848 | rr [8][64] @25408 | mbar 2xu64 @25920
#define ATTN_SMEM (25924*4)
#define CHUNK_BYTES (16*320 + 80*64*4)     // 5120 + 20480 = 25600

__global__ __launch_bounds__(256, 2) void attn_kernel(
    const float* __restrict__ attn_bias, int head)
{
    extern __shared__ float sm[];
    float* ks  = sm;
    float* vs  = sm + 2560;
    ull*   qs2 = (ull*)(sm + 12800);
    ull*   ps2 = (ull*)(sm + 14848);
    float* rr  = sm + 25408;
    unsigned mb0 = smem_u32(sm + 25920);
    unsigned mb1 = mb0 + 8;

    const int tid   = threadIdx.x;
    const int lane  = tid & 31;
    const int w     = tid >> 5;
    const int b     = blockIdx.y;
    const int n0    = blockIdx.x * 64;
    const int k0    = w * 10;
    const int dbase = w * 8;

    const float* kb  = g_k  + (size_t)b*16*NPIX;
    const float* vb  = g_vt + (size_t)b*NPIX*64;
    const float* bib = attn_bias + (size_t)head*NPIX;

    if (tid == 0){
        mbar_init(mb0, 1);
        mbar_init(mb1, 1);
    }
    __syncthreads();
    if (tid == 0){
        fence_async();
        // prefetch chunk 0 into buffer 0
        mbar_expect_tx(mb0, CHUNK_BYTES);
        #pragma unroll
        for (int kd = 0; kd < 16; kd++)
            cpbulk(smem_u32(&ks[kd*80]), &kb[(size_t)kd*NPIX], 320, mb0);
        cpbulk(smem_u32(vs), vb, 20480, mb0);
    }

    // q tile packed {q,q}, scale folded (overlaps chunk-0 load)
    for (int t = tid; t < 1024; t += 256){
        int kd = t >> 6, r = t & 63;
        float qv = g_q[((size_t)b*16 + kd)*NPIX + n0 + r] * SCALEF;
        qs2[t] = f2pack(qv, qv);
    }
    __syncthreads();   // ORDER qs2 writes before any warp's QK reads (R15 fix)

    ull out2[8];
    #pragma unroll
    for (int i = 0; i < 8; i++) out2[i] = 0ull;
    float rm0 = -1e30f, rm1 = -1e30f, rs0 = 0.f, rs1 = 0.f;

    for (int ch = 0; ch < 20; ch++){
        const int cur = ch & 1;
        const int m0  = ch * 80;
        const float* ksb = ks + cur*1280;
        const float* vsb = vs + cur*5120;

        mbar_wait(cur ? mb1 : mb0, (ch >> 1) & 1);   // buffers[cur] ready

        // ---- QK: 10 keys x 2 rows; bias (warp-uniform LDG) folded in ----
        ull a0[5], a1[5];
        #pragma unroll
        for (int t = 0; t < 5; t++){
            ull bb = *(const ull*)&bib[m0 + k0 + 2*t];
            a0[t] = bb; a1[t] = bb;
        }
        #pragma unroll
        for (int kd = 0; kd < 16; kd++){
            ull q2a = qs2[kd*64 + lane];
            ull q2b = qs2[kd*64 + lane + 32];
            const ull* kk = (const ull*)&ksb[kd*80 + k0];   // warp-uniform
            #pragma unroll
            for (int t = 0; t < 5; t++){
                ull kv = kk[t];
                a0[t] = ffma2(q2a, kv, a0[t]);
                a1[t] = ffma2(q2b, kv, a1[t]);
            }
        }
        float lm0 = -1e30f, lm1 = -1e30f;
        #pragma unroll
        for (int t = 0; t < 5; t++){
            float2 x0 = f2unpack(a0[t]); lm0 = fmaxf(lm0, fmaxf(x0.x, x0.y));
            float2 x1 = f2unpack(a1[t]); lm1 = fmaxf(lm1, fmaxf(x1.x, x1.y));
        }
        rr[w*64 + lane]      = lm0;
        rr[w*64 + lane + 32] = lm1;
        __syncthreads();                       // B: rr visible

        float nm0 = rm0, nm1 = rm1;
        #pragma unroll
        for (int j = 0; j < 8; j++){
            nm0 = fmaxf(nm0, rr[j*64 + lane]);
            nm1 = fmaxf(nm1, rr[j*64 + lane + 32]);
        }
        float c0 = __expf(rm0 - nm0), c1 = __expf(rm1 - nm1);
        rm0 = nm0; rm1 = nm1;
        rs0 *= c0; rs1 *= c1;
        {
            ull c20 = f2pack(c0, c0), c21 = f2pack(c1, c1);
            #pragma unroll
            for (int i = 0; i < 4; i++){
                out2[i]     = fmul2(out2[i],     c20);
                out2[i + 4] = fmul2(out2[i + 4], c21);
            }
        }
        // exp + store pre-packed probs
        #pragma unroll
        for (int t = 0; t < 5; t++){
            float2 x0 = f2unpack(a0[t]);
            float p00 = __expf(x0.x - nm0), p01 = __expf(x0.y - nm0);
            rs0 += p00 + p01;
            ps2[(k0 + 2*t)    *66 + lane] = f2pack(p00, p00);
            ps2[(k0 + 2*t + 1)*66 + lane] = f2pack(p01, p01);
            float2 x1 = f2unpack(a1[t]);
            float p10 = __expf(x1.x - nm1), p11 = __expf(x1.y - nm1);
            rs1 += p10 + p11;
            ps2[(k0 + 2*t)    *66 + lane + 32] = f2pack(p10, p10);
            ps2[(k0 + 2*t + 1)*66 + lane + 32] = f2pack(p11, p11);
        }

        // ---- prefetch next chunk into other buffer (single thread) ----
        // Safe: barrier B above ordered every thread's AV reads of chunk ch-1
        // (same buffer) before this issue.
        if (ch < 19 && tid == 0){
            const int m1 = m0 + 80;
            float* ksn = ks + (1-cur)*1280;
            float* vsn = vs + (1-cur)*5120;
            unsigned mbn = cur ? mb0 : mb1;
            mbar_expect_tx(mbn, CHUNK_BYTES);
            #pragma unroll
            for (int kd = 0; kd < 16; kd++)
                cpbulk(smem_u32(&ksn[kd*80]), &kb[(size_t)kd*NPIX + m1], 320, mbn);
            cpbulk(smem_u32(vsn), &vb[(size_t)m1*64], 20480, mbn);
        }
        __syncthreads();                       // C: ps2 visible to all warps

        // ---- AV: warp w accumulates dims [dbase, dbase+8) for 2 rows ----
        #pragma unroll 4
        for (int m = 0; m < 80; m++){
            ull p2a = ps2[m*66 + lane];
            ull p2b = ps2[m*66 + lane + 32];
            const float* vrow = &vsb[m*64 + dbase];       // warp-uniform
            ulonglong2 va  = *(const ulonglong2*)vrow;
            ulonglong2 vb2 = *(const ulonglong2*)(vrow + 4);
            out2[0] = ffma2(va.x,  p2a, out2[0]);
            out2[1] = ffma2(va.y,  p2a, out2[1]);
            out2[2] = ffma2(vb2.x, p2a, out2[2]);
            out2[3] = ffma2(vb2.y, p2a, out2[3]);
            out2[4] = ffma2(va.x,  p2b, out2[4]);
            out2[5] = ffma2(va.y,  p2b, out2[5]);
            out2[6] = ffma2(vb2.x, p2b, out2[6]);
            out2[7] = ffma2(vb2.y, p2b, out2[7]);
        }
    }

    // ---- row-sum across warps ----
    __syncthreads();
    rr[w*64 + lane]      = rs0;
    rr[w*64 + lane + 32] = rs1;
    __syncthreads();
    float t0 = 0.f, t1 = 0.f;
    #pragma unroll
    for (int j = 0; j < 8; j++){
        t0 += rr[j*64 + lane];
        t1 += rr[j*64 + lane + 32];
    }
    ull i20 = f2pack(1.0f/t0, 1.0f/t0);
    ull i21 = f2pack(1.0f/t1, 1.0f/t1);

    // ---- direct output write: warp owns its dims exclusively ----
    float* ob = g_cat + ((size_t)b*DIMC + head*64 + dbase)*NPIX + n0;
    #pragma unroll
    for (int jj = 0; jj < 4; jj++){
        float2 f0 = f2unpack(fmul2(out2[jj],     i20));
        float2 f1 = f2unpack(fmul2(out2[jj + 4], i21));
        ob[(size_t)(2*jj)    *NPIX + lane]      = f0.x;
        ob[(size_t)(2*jj + 1)*NPIX + lane]      = f0.y;
        ob[(size_t)(2*jj)    *NPIX + lane + 32] = f1.x;
        ob[(size_t)(2*jj + 1)*NPIX + lane + 32] = f1.y;
    }
}

// ================= 4) final 256x256 projection + BN + ReLU (f32x2) ==========
#define PROJ_SMEM (64*65*8 + 64*64*4)

__global__ __launch_bounds__(256) void proj_kernel(
    const float* __restrict__ W,
    const float* __restrict__ pg, const float* __restrict__ pb,
    const float* __restrict__ pm, const float* __restrict__ pvv,
    float* __restrict__ out)
{
    extern __shared__ float smp[];
    ull*   Wt2 = (ull*)smp;                // [64][65] packed {w,w}
    float* Xt  = smp + 64*65*2;            // [64][64]

    const int tid = threadIdx.x;
    const int n0 = blockIdx.x * 64;
    const int o0 = blockIdx.y * 64;
    const int b  = blockIdx.z;
    const int tn = tid % 16, to = tid / 16;

    ull acc2[4][2];
    #pragma unroll
    for (int i = 0; i < 4; i++){ acc2[i][0] = 0ull; acc2[i][1] = 0ull; }

    for (int c0 = 0; c0 < 256; c0 += 64){
        __syncthreads();
        for (int t = tid; t < 4096; t += 256){
            int i = t / 64, j = t % 64;
            float wv = W[(size_t)(o0 + i)*256 + c0 + j];
            Wt2[i*65 + j] = f2pack(wv, wv);
            Xt[i*64 + j]  = g_cat[((size_t)b*DIMC + c0 + i)*NPIX + n0 + j];
        }
        __syncthreads();
        for (int c = 0; c < 64; c++){
            ull bx01 = *(const ull*)&Xt[c*64 + tn*4];
            ull bx23 = *(const ull*)&Xt[c*64 + tn*4 + 2];
            #pragma unroll
            for (int i = 0; i < 4; i++){
                ull a2 = Wt2[(to*4 + i)*65 + c];
                acc2[i][0] = ffma2(a2, bx01, acc2[i][0]);
                acc2[i][1] = ffma2(a2, bx23, acc2[i][1]);
            }
        }
    }
    #pragma unroll
    for (int i = 0; i < 4; i++){
        int o = o0 + to*4 + i;
        float s  = pg[o] * rsqrtf(pvv[o] + EPSBN);
        float mu = pm[o], be = pb[o];
        float2 a = f2unpack(acc2[i][0]);
        float2 c = f2unpack(acc2[i][1]);
        float4 v4;
        v4.x = fmaxf((a.x-mu)*s + be, 0.f);
        v4.y = fmaxf((a.y-mu)*s + be, 0.f);
        v4.z = fmaxf((c.x-mu)*s + be, 0.f);
        v4.w = fmaxf((c.y-mu)*s + be, 0.f);
        *(float4*)&out[((size_t)b*DIMC + o)*NPIX + n0 + tn*4] = v4;
    }
}

// ================= launch ====================================================
extern "C" void kernel_launch(void* const* d_in, const int* in_sizes, int n_in,
                              void* d_out, int out_size)
{
    const float* x      = (const float*)d_in[0];
    const float* dw_w   = (const float*)d_in[1];
    const float* dw_g   = (const float*)d_in[2];
    const float* dw_b   = (const float*)d_in[3];
    const float* dw_m   = (const float*)d_in[4];
    const float* dw_v   = (const float*)d_in[5];
    const float* q_w    = (const float*)d_in[6];
    const float* q_g    = (const float*)d_in[7];
    const float* q_b    = (const float*)d_in[8];
    const float* q_m    = (const float*)d_in[9];
    const float* q_v    = (const float*)d_in[10];
    const float* k_w    = (const float*)d_in[11];
    const float* k_g    = (const float*)d_in[12];
    const float* k_b    = (const float*)d_in[13];
    const float* k_m    = (const float*)d_in[14];
    const float* k_v    = (const float*)d_in[15];
    const float* v_w    = (const float*)d_in[16];
    const float* v_g    = (const float*)d_in[17];
    const float* v_b    = (const float*)d_in[18];
    const float* v_m    = (const float*)d_in[19];
    const float* v_v    = (const float*)d_in[20];
    const float* proj_w = (const float*)d_in[21];
    const float* proj_g = (const float*)d_in[22];
    const float* proj_b = (const float*)d_in[23];
    const float* proj_m = (const float*)d_in[24];
    const float* proj_v = (const float*)d_in[25];
    const float* attn_b = (const float*)d_in[26];

    cudaFuncSetAttribute(qkv_kernel,
        cudaFuncAttributeMaxDynamicSharedMemorySize, QKV_SMEM);
    cudaFuncSetAttribute(attn_kernel,
        cudaFuncAttributeMaxDynamicSharedMemorySize, ATTN_SMEM);
    cudaFuncSetAttribute(proj_kernel,
        cudaFuncAttributeMaxDynamicSharedMemorySize, PROJ_SMEM);

    for (int head = 0; head < NHEADS; head++){
        dwconv_kernel<<<BATCH*HDC, 256>>>(
            x, dw_w, dw_g, dw_b, dw_m, dw_v, head);
        qkv_kernel<<<dim3(5, BATCH, 2), QKV_T, QKV_SMEM>>>(
            q_w, q_g, q_b, q_m, q_v,
            k_w, k_g, k_b, k_m, k_v,
            v_w, v_g, v_b, v_m, v_v, head);
        attn_kernel<<<dim3(25, BATCH), 256, ATTN_SMEM>>>(attn_b, head);
    }
    proj_kernel<<<dim3(25, 4, BATCH), 256, PROJ_SMEM>>>(
        proj_w, proj_g, proj_b, proj_m, proj_v, (float*)d_out);
}

// round 17
// speedup vs baseline: 1.5612x; 1.1940x over previous
#include <cuda_runtime.h>

// ---------------- problem constants ----------------
#define NHEADS 4
#define KDIM   16
#define RESV   40
#define DIMC   256
#define HDC    64
#define DV     64
#define NPIX   1600
#define BATCH  16
#define EPSBN  1e-5f
#define SCALEF 0.25f

typedef unsigned long long ull;

// ---------------- scratch (16B-aligned for bulk-copy sources) ----------------
__device__ __align__(16) float g_xi [BATCH*HDC*NPIX];
__device__ __align__(16) float g_q  [BATCH*KDIM*NPIX];
__device__ __align__(16) float g_k  [BATCH*KDIM*NPIX];
__device__ __align__(16) float g_vt [BATCH*NPIX*DV];      // [b][p][d]
__device__ __align__(16) float g_cat[BATCH*DIMC*NPIX];
__device__ float g_dummy;

// ---------------- f32x2 helpers ----------------
__device__ __forceinline__ ull f2pack(float x, float y){
    ull r; asm("mov.b64 %0, {%1, %2};" : "=l"(r) : "f"(x), "f"(y)); return r;
}
__device__ __forceinline__ float2 f2unpack(ull u){
    float2 r; asm("mov.b64 {%0, %1}, %2;" : "=f"(r.x), "=f"(r.y) : "l"(u)); return r;
}
__device__ __forceinline__ ull ffma2(ull a, ull b, ull c){
    ull r; asm("fma.rn.f32x2 %0, %1, %2, %3;" : "=l"(r) : "l"(a), "l"(b), "l"(c)); return r;
}
__device__ __forceinline__ ull fmul2(ull a, ull b){
    ull r; asm("mul.rn.f32x2 %0, %1, %2;" : "=l"(r) : "l"(a), "l"(b)); return r;
}

// ---------------- bulk-async + mbarrier helpers ----------------
__device__ __forceinline__ unsigned smem_u32(const void* p){
    return (unsigned)__cvta_generic_to_shared(p);
}
__device__ __forceinline__ void mbar_init(unsigned mbar, unsigned cnt){
    asm volatile("mbarrier.init.shared.b64 [%0], %1;" :: "r"(mbar), "r"(cnt) : "memory");
}
__device__ __forceinline__ void mbar_expect_tx(unsigned mbar, unsigned bytes){
    asm volatile("mbarrier.arrive.expect_tx.shared.b64 _, [%0], %1;"
                 :: "r"(mbar), "r"(bytes) : "memory");
}
__device__ __forceinline__ void mbar_wait(unsigned mbar, unsigned parity){
    asm volatile(
        "{\n\t.reg .pred P;\n\t"
        "W_%=:\n\t"
        "mbarrier.try_wait.parity.acquire.cta.shared::cta.b64 P, [%0], %1, 0x989680;\n\t"
        "@!P bra W_%=;\n\t"
        "}" :: "r"(mbar), "r"(parity) : "memory");
}
__device__ __forceinline__ void cpbulk(unsigned dst, const void* src,
                                       unsigned bytes, unsigned mbar){
    asm volatile(
        "cp.async.bulk.shared::cta.global.mbarrier::complete_tx::bytes [%0], [%1], %2, [%3];"
        :: "r"(dst), "l"(src), "r"(bytes), "r"(mbar) : "memory");
}
__device__ __forceinline__ void fence_async(){
    asm volatile("fence.proxy.async.shared::cta;" ::: "memory");
}

// ================= 0) ncu alignment shim (deterministic, ~2us) ==============
__global__ void prof_align_kernel(){
    if (threadIdx.x == 0) g_dummy = 1.0f;
}

// ================= 1) depthwise 5x5 conv + BN (+ cascade add) ================
__global__ __launch_bounds__(256) void dwconv_kernel(
    const float* __restrict__ x,
    const float* __restrict__ dw_w,
    const float* __restrict__ dw_g, const float* __restrict__ dw_b,
    const float* __restrict__ dw_m, const float* __restrict__ dw_v,
    int head)
{
    __shared__ float tile[44*44];
    __shared__ float wsh[25];

    const int tid = threadIdx.x;
    const int c   = blockIdx.x & 63;
    const int b   = blockIdx.x >> 6;
    const int ci  = head*HDC + c;

    const float* xs = x + ((size_t)b*DIMC + ci) * NPIX;
    const float s   = dw_g[ci] * rsqrtf(dw_v[ci] + EPSBN);
    const float bias = dw_b[ci] - dw_m[ci]*s;

    for (int t = tid; t < 44*44; t += 256) tile[t] = 0.f;
    if (tid < 25) wsh[tid] = dw_w[(size_t)ci*25 + tid] * s;
    __syncthreads();
    for (int t = tid; t < NPIX; t += 256){
        int h = t / 40, w = t - h*40;
        tile[(h+2)*44 + (w+2)] = xs[t];
    }
    __syncthreads();

    const float* prev = g_cat + ((size_t)b*DIMC + (head-1)*DV + c)*NPIX;
    float* xo = g_xi + ((size_t)b*HDC + c)*NPIX;

    for (int g = tid; g < 400; g += 256){
        int h  = g / 10;
        int w4 = (g - h*10) * 4;
        float o0 = bias, o1 = bias, o2 = bias, o3 = bias;
        #pragma unroll
        for (int ky = 0; ky < 5; ky++){
            const float* rp = &tile[(h+ky)*44 + w4];
            float4 A = *(const float4*)rp;
            float4 B = *(const float4*)(rp + 4);
            float a0=A.x,a1=A.y,a2=A.z,a3=A.w,a4=B.x,a5=B.y,a6=B.z,a7=B.w;
            float w0=wsh[ky*5+0], w1=wsh[ky*5+1], w2=wsh[ky*5+2],
                  w3=wsh[ky*5+3], w4v=wsh[ky*5+4];
            o0 = fmaf(a0,w0, fmaf(a1,w1, fmaf(a2,w2, fmaf(a3,w3, fmaf(a4,w4v, o0)))));
            o1 = fmaf(a1,w0, fmaf(a2,w1, fmaf(a3,w2, fmaf(a4,w3, fmaf(a5,w4v, o1)))));
            o2 = fmaf(a2,w0, fmaf(a3,w1, fmaf(a4,w2, fmaf(a5,w3, fmaf(a6,w4v, o2)))));
            o3 = fmaf(a3,w0, fmaf(a4,w1, fmaf(a5,w2, fmaf(a6,w3, fmaf(a7,w4v, o3)))));
        }
        int p = h*40 + w4;
        if (head > 0){
            float4 pv = *(const float4*)&prev[p];
            o0 += pv.x; o1 += pv.y; o2 += pv.z; o3 += pv.w;
        }
        float4 r; r.x=o0; r.y=o1; r.z=o2; r.w=o3;
        *(float4*)&xo[p] = r;
    }
}

// ================= 2) QKV projections + BN (f32x2) ===========================
#define QKV_T 320
#define QKV_SMEM (64*320*4 + 48*64*8)

__global__ __launch_bounds__(QKV_T) void qkv_kernel(
    const float* __restrict__ q_w, const float* __restrict__ q_g,
    const float* __restrict__ q_b, const float* __restrict__ q_m,
    const float* __restrict__ q_v,
    const float* __restrict__ k_w, const float* __restrict__ k_g,
    const float* __restrict__ k_b, const float* __restrict__ k_m,
    const float* __restrict__ k_v,
    const float* __restrict__ v_w, const float* __restrict__ v_g,
    const float* __restrict__ v_b, const float* __restrict__ v_m,
    const float* __restrict__ v_v,
    int head)
{
    extern __shared__ float sm[];
    float* xt  = sm;                       // [64][320]
    ull*   wsm = (ull*)(sm + 64*320);      // [48][64] packed {w,w}

    const int tid = threadIdx.x;
    const int b   = blockIdx.y;
    const int z   = blockIdx.z;
    const int p0  = blockIdx.x * 320;

    const float* xb = g_xi + (size_t)b*HDC*NPIX + p0;
    for (int t = tid; t < 64*320; t += QKV_T){
        int c = t / 320, pp2 = t % 320;
        xt[t] = xb[(size_t)c*NPIX + pp2];
    }
    for (int t = tid; t < 48*64; t += QKV_T){
        int jl = t / 64, cc = t % 64;
        int jr = z*48 + jl;
        float wv;
        if (jr < 16)      wv = q_w[(size_t)(head*16 + jr)      *64 + cc];
        else if (jr < 32) wv = k_w[(size_t)(head*16 + jr - 16) *64 + cc];
        else              wv = v_w[(size_t)(head*64 + jr - 32) *64 + cc];
        wsm[t] = f2pack(wv, wv);
    }
    __syncthreads();

    const int pp   = tid % 160;
    const int jsub = tid / 160;
    const int px   = p0 + 2*pp;

    for (int jg = 0; jg < 3; jg++){
        const int jl = jsub*24 + jg*8;
        ull acc2[8];
        #pragma unroll
        for (int k = 0; k < 8; k++) acc2[k] = 0ull;

        for (int c = 0; c < 64; c++){
            ull xv2 = *(const ull*)&xt[c*320 + 2*pp];
            const ull* wr = &wsm[jl*64 + c];
            #pragma unroll
            for (int k = 0; k < 8; k++)
                acc2[k] = ffma2(wr[k*64], xv2, acc2[k]);
        }
        #pragma unroll
        for (int k = 0; k < 8; k++){
            float2 a = f2unpack(acc2[k]);
            int jr = z*48 + jl + k;
            if (jr < 16){
                int q = head*16 + jr;
                float sc = q_g[q]*rsqrtf(q_v[q]+EPSBN);
                float mu = q_m[q], be = q_b[q];
                g_q[((size_t)b*16 + jr)*NPIX + px]     = (a.x-mu)*sc + be;
                g_q[((size_t)b*16 + jr)*NPIX + px + 1] = (a.y-mu)*sc + be;
            } else if (jr < 32){
                int q = head*16 + jr - 16;
                float sc = k_g[q]*rsqrtf(k_v[q]+EPSBN);
                float mu = k_m[q], be = k_b[q];
                g_k[((size_t)b*16 + (jr-16))*NPIX + px]     = (a.x-mu)*sc + be;
                g_k[((size_t)b*16 + (jr-16))*NPIX + px + 1] = (a.y-mu)*sc + be;
            } else {
                int d = jr - 32;
                int q = head*64 + d;
                float sc = v_g[q]*rsqrtf(v_v[q]+EPSBN);
                float mu = v_m[q], be = v_b[q];
                g_vt[((size_t)b*NPIX + px)    *64 + d] = (a.x-mu)*sc + be;
                g_vt[((size_t)b*NPIX + px + 1)*64 + d] = (a.y-mu)*sc + be;
            }
        }
    }
}

// ================= 3) fused flash attention (dim-split AV, occ=3) ============
// 64 query rows / block, chunk = 64 keys, 25 chunks, 8 warps.
// QK: warp w computes keys [w*8, w*8+8) for rows (lane, lane+32);
//     probs stored as plain float into ps[64][66] (packed at use in AV).
// AV: warp w owns dims [w*8, w*8+8) for ALL rows; V loads warp-uniform.
// smem cut to 64KB/block -> 3 blocks/SM (6 warps/SMSP) and a SINGLE wave
// (400 blocks <= 444 capacity). K/V double-buffered via cp.async.bulk.
// smem floats: ks 2x[16][64] @0 | vs 2x[64][64] @2048 | qs [16][64] @10240
//   | ps [64][66] @11264 | rr [8][64] @15488 | mbar 2xu64 @16000
#define ATTN_SMEM (16004*4)
#define CHUNK_BYTES (16*256 + 64*64*4)     // 4096 + 16384 = 20480

__global__ __launch_bounds__(256, 3) void attn_kernel(
    const float* __restrict__ attn_bias, int head)
{
    extern __shared__ float sm[];
    float* ks = sm;
    float* vs = sm + 2048;
    float* qs = sm + 10240;
    float* ps = sm + 11264;
    float* rr = sm + 15488;
    unsigned mb0 = smem_u32(sm + 16000);
    unsigned mb1 = mb0 + 8;

    const int tid   = threadIdx.x;
    const int lane  = tid & 31;
    const int w     = tid >> 5;
    const int b     = blockIdx.y;
    const int n0    = blockIdx.x * 64;
    const int k0    = w * 8;
    const int dbase = w * 8;

    const float* kb  = g_k  + (size_t)b*16*NPIX;
    const float* vb  = g_vt + (size_t)b*NPIX*64;
    const float* bib = attn_bias + (size_t)head*NPIX;

    if (tid == 0){
        mbar_init(mb0, 1);
        mbar_init(mb1, 1);
    }
    __syncthreads();
    if (tid == 0){
        fence_async();
        // prefetch chunk 0 into buffer 0
        mbar_expect_tx(mb0, CHUNK_BYTES);
        #pragma unroll
        for (int kd = 0; kd < 16; kd++)
            cpbulk(smem_u32(&ks[kd*64]), &kb[(size_t)kd*NPIX], 256, mb0);
        cpbulk(smem_u32(vs), vb, 16384, mb0);
    }

    // q tile (scale folded), overlaps chunk-0 load
    for (int t = tid; t < 1024; t += 256){
        int kd = t >> 6, r = t & 63;
        qs[t] = g_q[((size_t)b*16 + kd)*NPIX + n0 + r] * SCALEF;
    }
    __syncthreads();   // order qs writes before any warp's QK reads

    ull out2[8];
    #pragma unroll
    for (int i = 0; i < 8; i++) out2[i] = 0ull;
    float rm0 = -1e30f, rm1 = -1e30f, rs0 = 0.f, rs1 = 0.f;

    for (int ch = 0; ch < 25; ch++){
        const int cur = ch & 1;
        const int m0  = ch * 64;
        const float* ksb = ks + cur*1024;
        const float* vsb = vs + cur*4096;

        mbar_wait(cur ? mb1 : mb0, (ch >> 1) & 1);   // buffers[cur] ready

        // ---- QK: 8 keys x 2 rows; bias (warp-uniform LDG) folded in ----
        ull a0[4], a1[4];
        #pragma unroll
        for (int t = 0; t < 4; t++){
            ull bb = *(const ull*)&bib[m0 + k0 + 2*t];
            a0[t] = bb; a1[t] = bb;
        }
        #pragma unroll
        for (int kd = 0; kd < 16; kd++){
            float qa = qs[kd*64 + lane];
            float qb = qs[kd*64 + lane + 32];
            ull q2a = f2pack(qa, qa);
            ull q2b = f2pack(qb, qb);
            const ull* kk = (const ull*)&ksb[kd*64 + k0];   // warp-uniform
            #pragma unroll
            for (int t = 0; t < 4; t++){
                ull kv = kk[t];
                a0[t] = ffma2(q2a, kv, a0[t]);
                a1[t] = ffma2(q2b, kv, a1[t]);
            }
        }
        float lm0 = -1e30f, lm1 = -1e30f;
        #pragma unroll
        for (int t = 0; t < 4; t++){
            float2 x0 = f2unpack(a0[t]); lm0 = fmaxf(lm0, fmaxf(x0.x, x0.y));
            float2 x1 = f2unpack(a1[t]); lm1 = fmaxf(lm1, fmaxf(x1.x, x1.y));
        }
        rr[w*64 + lane]      = lm0;
        rr[w*64 + lane + 32] = lm1;
        __syncthreads();                       // B: rr visible

        float nm0 = rm0, nm1 = rm1;
        #pragma unroll
        for (int j = 0; j < 8; j++){
            nm0 = fmaxf(nm0, rr[j*64 + lane]);
            nm1 = fmaxf(nm1, rr[j*64 + lane + 32]);
        }
        float c0 = __expf(rm0 - nm0), c1 = __expf(rm1 - nm1);
        rm0 = nm0; rm1 = nm1;
        rs0 *= c0; rs1 *= c1;
        {
            ull c20 = f2pack(c0, c0), c21 = f2pack(c1, c1);
            #pragma unroll
            for (int i = 0; i < 4; i++){
                out2[i]     = fmul2(out2[i],     c20);
                out2[i + 4] = fmul2(out2[i + 4], c21);
            }
        }
        // exp + store plain-float probs
        #pragma unroll
        for (int t = 0; t < 4; t++){
            float2 x0 = f2unpack(a0[t]);
            float p00 = __expf(x0.x - nm0), p01 = __expf(x0.y - nm0);
            rs0 += p00 + p01;
            ps[(k0 + 2*t)    *66 + lane] = p00;
            ps[(k0 + 2*t + 1)*66 + lane] = p01;
            float2 x1 = f2unpack(a1[t]);
            float p10 = __expf(x1.x - nm1), p11 = __expf(x1.y - nm1);
            rs1 += p10 + p11;
            ps[(k0 + 2*t)    *66 + lane + 32] = p10;
            ps[(k0 + 2*t + 1)*66 + lane + 32] = p11;
        }

        // ---- prefetch next chunk into other buffer (single thread) ----
        // Safe: barrier B ordered every thread's AV reads of chunk ch-1
        // (same target buffer) before this issue.
        if (ch < 24 && tid == 0){
            const int m1 = m0 + 64;
            float* ksn = ks + (1-cur)*1024;
            float* vsn = vs + (1-cur)*4096;
            unsigned mbn = cur ? mb0 : mb1;
            mbar_expect_tx(mbn, CHUNK_BYTES);
            #pragma unroll
            for (int kd = 0; kd < 16; kd++)
                cpbulk(smem_u32(&ksn[kd*64]), &kb[(size_t)kd*NPIX + m1], 256, mbn);
            cpbulk(smem_u32(vsn), &vb[(size_t)m1*64], 16384, mbn);
        }
        __syncthreads();                       // C: ps visible to all warps

        // ---- AV: warp w accumulates dims [dbase, dbase+8) for 2 rows ----
        #pragma unroll 4
        for (int m = 0; m < 64; m++){
            float pa = ps[m*66 + lane];
            float pb = ps[m*66 + lane + 32];
            ull p2a = f2pack(pa, pa);
            ull p2b = f2pack(pb, pb);
            const float* vrow = &vsb[m*64 + dbase];       // warp-uniform
            ulonglong2 va  = *(const ulonglong2*)vrow;
            ulonglong2 vb2 = *(const ulonglong2*)(vrow + 4);
            out2[0] = ffma2(va.x,  p2a, out2[0]);
            out2[1] = ffma2(va.y,  p2a, out2[1]);
            out2[2] = ffma2(vb2.x, p2a, out2[2]);
            out2[3] = ffma2(vb2.y, p2a, out2[3]);
            out2[4] = ffma2(va.x,  p2b, out2[4]);
            out2[5] = ffma2(va.y,  p2b, out2[5]);
            out2[6] = ffma2(vb2.x, p2b, out2[6]);
            out2[7] = ffma2(vb2.y, p2b, out2[7]);
        }
    }

    // ---- row-sum across warps ----
    __syncthreads();
    rr[w*64 + lane]      = rs0;
    rr[w*64 + lane + 32] = rs1;
    __syncthreads();
    float t0 = 0.f, t1 = 0.f;
    #pragma unroll
    for (int j = 0; j < 8; j++){
        t0 += rr[j*64 + lane];
        t1 += rr[j*64 + lane + 32];
    }
    ull i20 = f2pack(1.0f/t0, 1.0f/t0);
    ull i21 = f2pack(1.0f/t1, 1.0f/t1);

    // ---- direct output write: warp owns its dims exclusively ----
    float* ob = g_cat + ((size_t)b*DIMC + head*64 + dbase)*NPIX + n0;
    #pragma unroll
    for (int jj = 0; jj < 4; jj++){
        float2 f0 = f2unpack(fmul2(out2[jj],     i20));
        float2 f1 = f2unpack(fmul2(out2[jj + 4], i21));
        ob[(size_t)(2*jj)    *NPIX + lane]      = f0.x;
        ob[(size_t)(2*jj + 1)*NPIX + lane]      = f0.y;
        ob[(size_t)(2*jj)    *NPIX + lane + 32] = f1.x;
        ob[(size_t)(2*jj + 1)*NPIX + lane + 32] = f1.y;
    }
}

// ================= 4) final 256x256 projection + BN + ReLU (f32x2) ==========
#define PROJ_SMEM (64*65*8 + 64*64*4)

__global__ __launch_bounds__(256) void proj_kernel(
    const float* __restrict__ W,
    const float* __restrict__ pg, const float* __restrict__ pb,
    const float* __restrict__ pm, const float* __restrict__ pvv,
    float* __restrict__ out)
{
    extern __shared__ float smp[];
    ull*   Wt2 = (ull*)smp;                // [64][65] packed {w,w}
    float* Xt  = smp + 64*65*2;            // [64][64]

    const int tid = threadIdx.x;
    const int n0 = blockIdx.x * 64;
    const int o0 = blockIdx.y * 64;
    const int b  = blockIdx.z;
    const int tn = tid % 16, to = tid / 16;

    ull acc2[4][2];
    #pragma unroll
    for (int i = 0; i < 4; i++){ acc2[i][0] = 0ull; acc2[i][1] = 0ull; }

    for (int c0 = 0; c0 < 256; c0 += 64){
        __syncthreads();
        for (int t = tid; t < 4096; t += 256){
            int i = t / 64, j = t % 64;
            float wv = W[(size_t)(o0 + i)*256 + c0 + j];
            Wt2[i*65 + j] = f2pack(wv, wv);
            Xt[i*64 + j]  = g_cat[((size_t)b*DIMC + c0 + i)*NPIX + n0 + j];
        }
        __syncthreads();
        for (int c = 0; c < 64; c++){
            ull bx01 = *(const ull*)&Xt[c*64 + tn*4];
            ull bx23 = *(const ull*)&Xt[c*64 + tn*4 + 2];
            #pragma unroll
            for (int i = 0; i < 4; i++){
                ull a2 = Wt2[(to*4 + i)*65 + c];
                acc2[i][0] = ffma2(a2, bx01, acc2[i][0]);
                acc2[i][1] = ffma2(a2, bx23, acc2[i][1]);
            }
        }
    }
    #pragma unroll
    for (int i = 0; i < 4; i++){
        int o = o0 + to*4 + i;
        float s  = pg[o] * rsqrtf(pvv[o] + EPSBN);
        float mu = pm[o], be = pb[o];
        float2 a = f2unpack(acc2[i][0]);
        float2 c = f2unpack(acc2[i][1]);
        float4 v4;
        v4.x = fmaxf((a.x-mu)*s + be, 0.f);
        v4.y = fmaxf((a.y-mu)*s + be, 0.f);
        v4.z = fmaxf((c.x-mu)*s + be, 0.f);
        v4.w = fmaxf((c.y-mu)*s + be, 0.f);
        *(float4*)&out[((size_t)b*DIMC + o)*NPIX + n0 + tn*4] = v4;
    }
}

// ================= launch ====================================================
extern "C" void kernel_launch(void* const* d_in, const int* in_sizes, int n_in,
                              void* d_out, int out_size)
{
    const float* x      = (const float*)d_in[0];
    const float* dw_w   = (const float*)d_in[1];
    const float* dw_g   = (const float*)d_in[2];
    const float* dw_b   = (const float*)d_in[3];
    const float* dw_m   = (const float*)d_in[4];
    const float* dw_v   = (const float*)d_in[5];
    const float* q_w    = (const float*)d_in[6];
    const float* q_g    = (const float*)d_in[7];
    const float* q_b    = (const float*)d_in[8];
    const float* q_m    = (const float*)d_in[9];
    const float* q_v    = (const float*)d_in[10];
    const float* k_w    = (const float*)d_in[11];
    const float* k_g    = (const float*)d_in[12];
    const float* k_b    = (const float*)d_in[13];
    const float* k_m    = (const float*)d_in[14];
    const float* k_v    = (const float*)d_in[15];
    const float* v_w    = (const float*)d_in[16];
    const float* v_g    = (const float*)d_in[17];
    const float* v_b    = (const float*)d_in[18];
    const float* v_m    = (const float*)d_in[19];
    const float* v_v    = (const float*)d_in[20];
    const float* proj_w = (const float*)d_in[21];
    const float* proj_g = (const float*)d_in[22];
    const float* proj_b = (const float*)d_in[23];
    const float* proj_m = (const float*)d_in[24];
    const float* proj_v = (const float*)d_in[25];
    const float* attn_b = (const float*)d_in[26];

    cudaFuncSetAttribute(qkv_kernel,
        cudaFuncAttributeMaxDynamicSharedMemorySize, QKV_SMEM);
    cudaFuncSetAttribute(attn_kernel,
        cudaFuncAttributeMaxDynamicSharedMemorySize, ATTN_SMEM);
    cudaFuncSetAttribute(proj_kernel,
        cudaFuncAttributeMaxDynamicSharedMemorySize, PROJ_SMEM);

    // shift the fixed-offset ncu capture window toward attn_kernel
    prof_align_kernel<<<1, 32>>>();

    for (int head = 0; head < NHEADS; head++){
        dwconv_kernel<<<BATCH*HDC, 256>>>(
            x, dw_w, dw_g, dw_b, dw_m, dw_v, head);
        qkv_kernel<<<dim3(5, BATCH, 2), QKV_T, QKV_SMEM>>>(
            q_w, q_g, q_b, q_m, q_v,
            k_w, k_g, k_b, k_m, k_v,
            v_w, v_g, v_b, v_m, v_v, head);
        attn_kernel<<<dim3(25, BATCH), 256, ATTN_SMEM>>>(attn_b, head);
    }
    proj_kernel<<<dim3(25, 4, BATCH), 256, PROJ_SMEM>>>(
        proj_w, proj_g, proj_b, proj_m, proj_v, (float*)d_out);
}